// round 13
// baseline (speedup 1.0000x reference)
#include <cuda_runtime.h>
#include <cuda_bf16.h>
#include <cstdint>
#include <math.h>

#define BSZ   4096
#define NROWS 8192
#define DIM   128
#define TS    128
#define INV_T     (1.0f / 0.07f)
#define EXP2_SCL  (1.4426950408889634f / 0.07f)   // log2(e)/T
#define NTILE 2080
#define CAP   4194304
#define NCTA  148
#define NTHR  512
#define NWARP (NCTA * NTHR / 32)

// ---------------- scratch (__device__ globals; no allocs allowed) ----------
__device__ __nv_bfloat16  g_Uhi[NROWS * DIM];
__device__ float          g_S  [NROWS];
__device__ int            g_lab[BSZ];
__device__ int            g_npairs;
__device__ uint2          g_pairs[CAP];     // {i<<13|j, bits(logit)}
__device__ double         g_loss;
__device__ int            g_bar_cnt;        // grid barrier (self-resetting)
__device__ int            g_bar_gen;

// ---------------- helpers ---------------------------------------------------
__device__ __forceinline__ float ex2_fast(float x) {
    float r;
    asm("ex2.approx.ftz.f32 %0, %1;" : "=f"(r) : "f"(x));
    return r;
}
__device__ __forceinline__ uint32_t smem_u32(const void* p) {
    uint32_t a;
    asm("{ .reg .u64 t; cvta.to.shared.u64 t, %1; cvt.u32.u64 %0, t; }"
        : "=r"(a) : "l"(p));
    return a;
}
__device__ __forceinline__ void cp_async16(uint32_t saddr, const void* gp) {
    uint64_t ga;
    asm("cvta.to.global.u64 %0, %1;" : "=l"(ga) : "l"(gp));
    asm volatile("cp.async.cg.shared.global [%0], [%1], 16;"
                 :: "r"(saddr), "l"(ga));
}
#define CP_COMMIT()  asm volatile("cp.async.commit_group;" ::: "memory")
#define CP_WAIT(n)   asm volatile("cp.async.wait_group %0;" :: "n"(n) : "memory")

__device__ __forceinline__ void ldmatrix_x4(uint32_t* r, uint32_t addr) {
    asm volatile("ldmatrix.sync.aligned.m8n8.x4.shared.b16 {%0,%1,%2,%3}, [%4];"
                 : "=r"(r[0]), "=r"(r[1]), "=r"(r[2]), "=r"(r[3]) : "r"(addr));
}
__device__ __forceinline__ void mma_16816_bf16(float* d, const uint32_t* a,
                                               const uint32_t* b) {
    asm volatile(
        "mma.sync.aligned.m16n8k16.row.col.f32.bf16.bf16.f32 "
        "{%0,%1,%2,%3}, {%4,%5,%6,%7}, {%8,%9}, {%0,%1,%2,%3};"
        : "+f"(d[0]), "+f"(d[1]), "+f"(d[2]), "+f"(d[3])
        : "r"(a[0]), "r"(a[1]), "r"(a[2]), "r"(a[3]), "r"(b[0]), "r"(b[1]));
}

// grid-wide barrier: valid because all NCTA CTAs are co-resident (1 CTA/SM)
__device__ __forceinline__ void grid_sync() {
    __syncthreads();
    if (threadIdx.x == 0) {
        int gen = *((volatile int*)&g_bar_gen);
        __threadfence();
        int arr = atomicAdd(&g_bar_cnt, 1);
        if (arr == NCTA - 1) {
            g_bar_cnt = 0;
            __threadfence();
            atomicExch(&g_bar_gen, gen + 1);
        } else {
            while (*((volatile int*)&g_bar_gen) == gen) { }
        }
        __threadfence();
    }
    __syncthreads();
}

// tile index t (0..2079) -> (bi, bj) in row-major upper triangle
__device__ __forceinline__ void tile_map(int t, int& bi, int& bj) {
    int u = NTILE - t;
    float mf = (sqrtf(8.0f * (float)u + 1.0f) - 1.0f) * 0.5f;
    int m = (int)ceilf(mf);
    while (m * (m + 1) / 2 < u) m++;
    while (m > 1 && (m - 1) * m / 2 >= u) m--;
    bi = 64 - m;
    int off = bi * 64 - bi * (bi - 1) / 2;
    bj = bi + (t - off);
}

// ---------------------------------------------------------------------------
// SMEM layout for GEMM phase
// ---------------------------------------------------------------------------
#define TILE_B   32768
#define SM_TOTAL (4 * TILE_B)          // A + 3 B ring buffers = 131072
extern __shared__ char smemB[];

__device__ __forceinline__ uint32_t sw_off(int row, int k_elem) {
    int chunk = k_elem >> 3;
    int within = k_elem & 7;
    return (uint32_t)(row * 256 + ((chunk ^ (row & 7)) << 4) + within * 2);
}

__device__ __forceinline__ void prefetch_tile(uint32_t dst,
                                              const __nv_bfloat16* hi,
                                              int tid) {
    #pragma unroll
    for (int it = 0; it < 4; it++) {
        int idx = tid + it * 512;      // 2048 chunks of 16B
        int row = idx >> 4;
        int c   = idx & 15;
        cp_async16(dst + row * 256 + ((c ^ (row & 7)) << 4),
                   (const char*)hi + row * 256 + c * 16);
    }
}

// load A/B fragments for one 16-wide k-step
__device__ __forceinline__ void load_frags(uint32_t sA, uint32_t bb, int ks,
                                           int m_base, int n_base, int lane,
                                           uint32_t af[2][4], uint32_t bf[4][2]) {
    int k0 = ks * 16;
    #pragma unroll
    for (int mt = 0; mt < 2; mt++) {
        int row = m_base + mt * 16 + (lane & 15);
        int k   = k0 + ((lane >> 4) << 3);
        ldmatrix_x4(af[mt], sA + sw_off(row, k));
    }
    #pragma unroll
    for (int np = 0; np < 2; np++) {
        uint32_t r4[4];
        int n = n_base + np * 16 + (lane & 7) + ((lane >> 4) << 3);
        int k = k0 + (((lane >> 3) & 1) << 3);
        ldmatrix_x4(r4, bb + sw_off(n, k));
        bf[np * 2 + 0][0] = r4[0]; bf[np * 2 + 0][1] = r4[1];
        bf[np * 2 + 1][0] = r4[2]; bf[np * 2 + 1][1] = r4[3];
    }
}

// ---------------------------------------------------------------------------
// Single persistent kernel: prep -> barrier -> GEMM/negsum -> barrier ->
// pair loss -> barrier -> scalar write
// ---------------------------------------------------------------------------
__global__ __launch_bounds__(NTHR, 1) void supcon_kernel(
        const float* __restrict__ feat,
        const void* __restrict__ labels_raw,
        float* __restrict__ out) {
    __shared__ int s_lab[BSZ];         // 16 KB static label cache

    int cta  = blockIdx.x;
    int tid  = threadIdx.x;
    int wid  = tid >> 5;
    int lane = tid & 31;
    int gt   = cta * NTHR + tid;
    int gw   = gt >> 5;

    // ================= phase 0: init + labels + normalize ==================
    {
        __shared__ int s_is64;
        if (tid == 0) {
            const int* li = (const int*)labels_raw;
            bool is64 = true;
            #pragma unroll
            for (int q = 1; q < 16; q += 2) is64 &= (li[q] == 0);
            s_is64 = is64 ? 1 : 0;
        }
        if (gt < NROWS) g_S[gt] = 0.0f;
        if (gt == 0) { g_loss = 0.0; g_npairs = 0; }
        __syncthreads();
        if (gt < BSZ)
            g_lab[gt] = s_is64 ? (int)((const long long*)labels_raw)[gt]
                               : ((const int*)labels_raw)[gt];

        for (int i = gw; i < NROWS; i += NWARP) {
            int v = i >> 12;
            int b = i & (BSZ - 1);
            const float4* src = (const float4*)&feat[(size_t)(b * 2 + v) * DIM];
            float4 f = src[lane];
            float ss = f.x * f.x + f.y * f.y + f.z * f.z + f.w * f.w;
            #pragma unroll
            for (int o = 16; o > 0; o >>= 1)
                ss += __shfl_xor_sync(0xffffffffu, ss, o);
            float rn = rsqrtf(ss);
            float u[4] = { f.x * rn, f.y * rn, f.z * rn, f.w * rn };
            __nv_bfloat16 hi[4];
            #pragma unroll
            for (int q = 0; q < 4; q++) hi[q] = __float2bfloat16(u[q]);
            ((uint2*)&g_Uhi[(size_t)i * DIM])[lane] =
                make_uint2(((uint32_t*)hi)[0], ((uint32_t*)hi)[1]);
        }
    }
    grid_sync();

    // ================= phase 1: GEMM + neg-sum + pair harvest ==============
    {
        int s = cta * 14 + min(cta, 8);
        int e = s + 14 + (cta < 8 ? 1 : 0);

        uint32_t sA = smem_u32(smemB);

        int wm = wid & 3, wn = wid >> 2;            // 4x4 warp grid
        int m_base = wm * 32, n_base = wn * 32;
        int gid = lane >> 2, qid = lane & 3;

        int cur_bi = -1, prev_I0 = -1;
        float rsa[2][2] = {{0, 0}, {0, 0}};

        #pragma unroll
        for (int q = 0; q < BSZ / NTHR; q++)
            s_lab[tid + q * NTHR] = g_lab[tid + q * NTHR];

        {
            int bi0, bj0; tile_map(s, bi0, bj0);
            prefetch_tile(sA + TILE_B * (1 + s % 3),
                          &g_Uhi[(size_t)bj0 * TS * DIM], tid);
            CP_COMMIT();
        }

        #pragma unroll 1
        for (int t = s; t < e; t++) {
            int bi, bj; tile_map(t, bi, bj);
            if (bi != cur_bi) {
                if (prev_I0 >= 0) {
                    #pragma unroll
                    for (int mt = 0; mt < 2; mt++)
                        #pragma unroll
                        for (int h = 0; h < 2; h++) {
                            float v = rsa[mt][h];
                            v += __shfl_xor_sync(0xffffffffu, v, 1);
                            v += __shfl_xor_sync(0xffffffffu, v, 2);
                            if (qid == 0)
                                atomicAdd(&g_S[prev_I0 + m_base + mt * 16 + h * 8 + gid], v);
                            rsa[mt][h] = 0.0f;
                        }
                }
                __syncthreads();   // all warps done reading sA before overwrite
                prefetch_tile(sA, &g_Uhi[(size_t)bi * TS * DIM], tid);
                CP_COMMIT();
                cur_bi = bi;
                prev_I0 = bi * TS;
            }
            if (t + 1 < e) {
                int bi2, bj2; tile_map(t + 1, bi2, bj2);
                prefetch_tile(sA + TILE_B * (1 + (t + 1) % 3),
                              &g_Uhi[(size_t)bj2 * TS * DIM], tid);
                CP_COMMIT();
                CP_WAIT(1);
            } else {
                CP_WAIT(0);
            }
            __syncthreads();

            bool diag = (bi == bj);
            int I0 = bi * TS, J0 = bj * TS;
            uint32_t bb = sA + TILE_B * (1 + t % 3);

            float acc[2][4][4];
            #pragma unroll
            for (int mt = 0; mt < 2; mt++)
                #pragma unroll
                for (int nt = 0; nt < 4; nt++)
                    #pragma unroll
                    for (int q = 0; q < 4; q++) acc[mt][nt][q] = 0.0f;

            uint32_t afr[2][2][4], bfr[2][4][2];
            load_frags(sA, bb, 0, m_base, n_base, lane, afr[0], bfr[0]);
            #pragma unroll
            for (int ks = 0; ks < 8; ks++) {
                int cur = ks & 1;
                if (ks < 7)
                    load_frags(sA, bb, ks + 1, m_base, n_base, lane,
                               afr[cur ^ 1], bfr[cur ^ 1]);
                #pragma unroll
                for (int mt = 0; mt < 2; mt++)
                    #pragma unroll
                    for (int nt = 0; nt < 4; nt++)
                        mma_16816_bf16(acc[mt][nt], afr[cur][mt], bfr[cur][nt]);
            }

            // ---- epilogue ----
            int la[2][2], lb[4][2];
            #pragma unroll
            for (int mt = 0; mt < 2; mt++)
                #pragma unroll
                for (int h = 0; h < 2; h++)
                    la[mt][h] = s_lab[(I0 + m_base + mt * 16 + h * 8 + gid) & (BSZ - 1)];
            #pragma unroll
            for (int nt = 0; nt < 4; nt++)
                #pragma unroll
                for (int qq = 0; qq < 2; qq++)
                    lb[nt][qq] = s_lab[(J0 + n_base + nt * 8 + qid * 2 + qq) & (BSZ - 1)];

            uint32_t posmask = 0u;
            if (!diag) {
                float cs[4][2];
                #pragma unroll
                for (int nt = 0; nt < 4; nt++) cs[nt][0] = cs[nt][1] = 0.0f;
                #pragma unroll
                for (int mt = 0; mt < 2; mt++)
                    #pragma unroll
                    for (int nt = 0; nt < 4; nt++)
                        #pragma unroll
                        for (int h = 0; h < 2; h++)
                            #pragma unroll
                            for (int qq = 0; qq < 2; qq++) {
                                float d = acc[mt][nt][h * 2 + qq];
                                bool same = (la[mt][h] == lb[nt][qq]);
                                float ev = same ? 0.0f : ex2_fast(d * EXP2_SCL);
                                rsa[mt][h] += ev;
                                cs[nt][qq] += ev;
                                if (same)
                                    posmask |= 1u << (mt * 16 + nt * 4 + h * 2 + qq);
                            }
                #pragma unroll
                for (int nt = 0; nt < 4; nt++)
                    #pragma unroll
                    for (int qq = 0; qq < 2; qq++) {
                        float v = cs[nt][qq];
                        v += __shfl_xor_sync(0xffffffffu, v, 4);
                        v += __shfl_xor_sync(0xffffffffu, v, 8);
                        v += __shfl_xor_sync(0xffffffffu, v, 16);
                        if (gid == 0)
                            atomicAdd(&g_S[J0 + n_base + nt * 8 + qid * 2 + qq], v);
                    }
            } else {
                #pragma unroll
                for (int mt = 0; mt < 2; mt++)
                    #pragma unroll
                    for (int nt = 0; nt < 4; nt++)
                        #pragma unroll
                        for (int h = 0; h < 2; h++)
                            #pragma unroll
                            for (int qq = 0; qq < 2; qq++) {
                                int rloc = m_base + mt * 16 + h * 8 + gid;
                                int cloc = n_base + nt * 8 + qid * 2 + qq;
                                float d = acc[mt][nt][h * 2 + qq];
                                bool same = (la[mt][h] == lb[nt][qq]);
                                float ev = same ? 0.0f : ex2_fast(d * EXP2_SCL);
                                rsa[mt][h] += ev;
                                if (same && rloc < cloc)
                                    posmask |= 1u << (mt * 16 + nt * 4 + h * 2 + qq);
                            }
            }

            // ---- warp-aggregated pair append ----
            {
                int cnt = __popc(posmask);
                int inc = cnt;
                #pragma unroll
                for (int o = 1; o < 32; o <<= 1) {
                    int v = __shfl_up_sync(0xffffffffu, inc, o);
                    if (lane >= o) inc += v;
                }
                int excl  = inc - cnt;
                int total = __shfl_sync(0xffffffffu, inc, 31);
                if (total > 0) {
                    int base2 = 0;
                    if (lane == 31) base2 = atomicAdd(&g_npairs, total);
                    base2 = __shfl_sync(0xffffffffu, base2, 31);
                    int slot = base2 + excl;
                    if (posmask) {
                        #pragma unroll
                        for (int mt = 0; mt < 2; mt++)
                            #pragma unroll
                            for (int nt = 0; nt < 4; nt++)
                                #pragma unroll
                                for (int h = 0; h < 2; h++)
                                    #pragma unroll
                                    for (int qq = 0; qq < 2; qq++) {
                                        int eidx = mt * 16 + nt * 4 + h * 2 + qq;
                                        if ((posmask >> eidx) & 1u) {
                                            int rloc = m_base + mt * 16 + h * 8 + gid;
                                            int cloc = n_base + nt * 8 + qid * 2 + qq;
                                            float l = acc[mt][nt][h * 2 + qq] * INV_T;
                                            if (slot < CAP) {
                                                uint32_t ij = ((uint32_t)(I0 + rloc) << 13)
                                                             | (uint32_t)(J0 + cloc);
                                                g_pairs[slot] =
                                                    make_uint2(ij, __float_as_uint(l));
                                            }
                                            slot++;
                                        }
                                    }
                    }
                }
            }
        }

        // final row-sum flush
        if (prev_I0 >= 0) {
            #pragma unroll
            for (int mt = 0; mt < 2; mt++)
                #pragma unroll
                for (int h = 0; h < 2; h++) {
                    float v = rsa[mt][h];
                    v += __shfl_xor_sync(0xffffffffu, v, 1);
                    v += __shfl_xor_sync(0xffffffffu, v, 2);
                    if (qid == 0)
                        atomicAdd(&g_S[prev_I0 + m_base + mt * 16 + h * 8 + gid], v);
                }
        }
    }
    grid_sync();

    // ================= phase 2: positive-pair loss =========================
    {
        int n = min(g_npairs, CAP);
        float sum = 0.0f;
        for (int idx = gt; idx < n; idx += NCTA * NTHR) {
            uint2 en = g_pairs[idx];
            int i = (int)(en.x >> 13);
            int j = (int)(en.x & 8191u);
            float l = __uint_as_float(en.y);
            float ev = __expf(l);
            sum += 2.0f * l - __logf(g_S[i] + ev) - __logf(g_S[j] + ev);
        }
        #pragma unroll
        for (int o = 16; o > 0; o >>= 1)
            sum += __shfl_xor_sync(0xffffffffu, sum, o);
        __shared__ float ws[NTHR / 32];
        if (lane == 0) ws[wid] = sum;
        __syncthreads();
        if (tid == 0) {
            float b = 0.0f;
            #pragma unroll
            for (int w = 0; w < NTHR / 32; w++) b += ws[w];
            if (b != 0.0f) atomicAdd(&g_loss, (double)b);
        }
    }
    grid_sync();

    if (gt == 0) out[0] = (float)(-g_loss / (double)NROWS);
}

extern "C" void kernel_launch(void* const* d_in, const int* in_sizes, int n_in,
                              void* d_out, int out_size) {
    const float* feat   = (const float*)d_in[0];
    const void*  labels = d_in[1];
    float*       out    = (float*)d_out;

    cudaFuncSetAttribute(supcon_kernel,
                         cudaFuncAttributeMaxDynamicSharedMemorySize, SM_TOTAL);
    supcon_kernel<<<NCTA, NTHR, SM_TOTAL>>>(feat, labels, out);
}

// round 14
// speedup vs baseline: 1.1520x; 1.1520x over previous
#include <cuda_runtime.h>
#include <cuda_bf16.h>
#include <cstdint>
#include <math.h>

#define BSZ   4096
#define NROWS 8192
#define DIM   128
#define TS    128
#define INV_T     (1.0f / 0.07f)
#define EXP2_SCL  (1.4426950408889634f / 0.07f)   // log2(e)/T
#define NTILE 2080
#define NCTA  148
#define REG   32768                   // pairs per CTA region

// ---------------- scratch (__device__ globals; no allocs allowed) ----------
__device__ __nv_bfloat16  g_Uhi[NROWS * DIM];
__device__ float          g_S  [NROWS];
__device__ int            g_lab[BSZ];
__device__ int            g_cta_np[NCTA];
__device__ int            g_done;
__device__ uint2          g_pairs[NCTA * REG];   // {i<<13|j, bits(logit)}
__device__ double         g_loss;

// ---------------- helpers ---------------------------------------------------
__device__ __forceinline__ float ex2_fast(float x) {
    float r;
    asm("ex2.approx.ftz.f32 %0, %1;" : "=f"(r) : "f"(x));
    return r;
}
__device__ __forceinline__ uint32_t smem_u32(const void* p) {
    uint32_t a;
    asm("{ .reg .u64 t; cvta.to.shared.u64 t, %1; cvt.u32.u64 %0, t; }"
        : "=r"(a) : "l"(p));
    return a;
}
__device__ __forceinline__ void cp_async16(uint32_t saddr, const void* gp) {
    uint64_t ga;
    asm("cvta.to.global.u64 %0, %1;" : "=l"(ga) : "l"(gp));
    asm volatile("cp.async.cg.shared.global [%0], [%1], 16;"
                 :: "r"(saddr), "l"(ga));
}
#define CP_COMMIT()  asm volatile("cp.async.commit_group;" ::: "memory")
#define CP_WAIT(n)   asm volatile("cp.async.wait_group %0;" :: "n"(n) : "memory")

__device__ __forceinline__ void ldmatrix_x4(uint32_t* r, uint32_t addr) {
    asm volatile("ldmatrix.sync.aligned.m8n8.x4.shared.b16 {%0,%1,%2,%3}, [%4];"
                 : "=r"(r[0]), "=r"(r[1]), "=r"(r[2]), "=r"(r[3]) : "r"(addr));
}
__device__ __forceinline__ void mma_16816_bf16(float* d, const uint32_t* a,
                                               const uint32_t* b) {
    asm volatile(
        "mma.sync.aligned.m16n8k16.row.col.f32.bf16.bf16.f32 "
        "{%0,%1,%2,%3}, {%4,%5,%6,%7}, {%8,%9}, {%0,%1,%2,%3};"
        : "+f"(d[0]), "+f"(d[1]), "+f"(d[2]), "+f"(d[3])
        : "r"(a[0]), "r"(a[1]), "r"(a[2]), "r"(a[3]), "r"(b[0]), "r"(b[1]));
}

// tile index t (0..2079) -> (bi, bj) in row-major upper triangle
__device__ __forceinline__ void tile_map(int t, int& bi, int& bj) {
    int u = NTILE - t;
    float mf = (sqrtf(8.0f * (float)u + 1.0f) - 1.0f) * 0.5f;
    int m = (int)ceilf(mf);
    while (m * (m + 1) / 2 < u) m++;
    while (m > 1 && (m - 1) * m / 2 >= u) m--;
    bi = 64 - m;
    int off = bi * 64 - bi * (bi - 1) / 2;
    bj = bi + (t - off);
}

// ---------------------------------------------------------------------------
// Kernel A: normalize rows; emit bf16 copy; zero accumulators
// ---------------------------------------------------------------------------
__global__ void prep_kernel(const float* __restrict__ feat,
                            const void* __restrict__ labels_raw) {
    __shared__ int s_is64;
    int t    = blockIdx.x * blockDim.x + threadIdx.x;
    int warp = t >> 5;
    int lane = t & 31;

    if (threadIdx.x == 0) {
        const int* li = (const int*)labels_raw;
        bool is64 = true;
        #pragma unroll
        for (int q = 1; q < 16; q += 2) is64 &= (li[q] == 0);
        s_is64 = is64 ? 1 : 0;
    }
    if (t < NROWS) g_S[t] = 0.0f;
    if (t == 0) { g_loss = 0.0; g_done = 0; }
    __syncthreads();
    if (t < BSZ) {
        g_lab[t] = s_is64 ? (int)((const long long*)labels_raw)[t]
                          : ((const int*)labels_raw)[t];
    }

    if (warp >= NROWS) return;
    int i = warp;
    int v = i >> 12;
    int b = i & (BSZ - 1);
    const float4* src = (const float4*)&feat[(size_t)(b * 2 + v) * DIM];
    float4 f = src[lane];
    float ss = f.x * f.x + f.y * f.y + f.z * f.z + f.w * f.w;
    #pragma unroll
    for (int o = 16; o > 0; o >>= 1) ss += __shfl_xor_sync(0xffffffffu, ss, o);
    float rn = rsqrtf(ss);
    float u[4] = { f.x * rn, f.y * rn, f.z * rn, f.w * rn };

    __nv_bfloat16 hi[4];
    #pragma unroll
    for (int q = 0; q < 4; q++) hi[q] = __float2bfloat16(u[q]);
    ((uint2*)&g_Uhi[(size_t)i * DIM])[lane] =
        make_uint2(((uint32_t*)hi)[0], ((uint32_t*)hi)[1]);
}

// ---------------------------------------------------------------------------
// Kernel B: persistent bf16 mma.sync GEMM, 512 threads (16 warps, 32x32
// warp tiles). A reused across a row; B in a 3-deep cp.async ring.
// Labels in SMEM; pipelined k-loop; pair append via SMEM counter into
// per-CTA region (no global atomics, no scan).
// ---------------------------------------------------------------------------
#define TILE_B   32768
#define SM_TOTAL (4 * TILE_B)          // A + 3 B ring buffers = 131072
extern __shared__ char smemB[];

__device__ __forceinline__ uint32_t sw_off(int row, int k_elem) {
    int chunk = k_elem >> 3;
    int within = k_elem & 7;
    return (uint32_t)(row * 256 + ((chunk ^ (row & 7)) << 4) + within * 2);
}

__device__ __forceinline__ void prefetch_tile(uint32_t dst,
                                              const __nv_bfloat16* hi,
                                              int tid) {
    #pragma unroll
    for (int it = 0; it < 4; it++) {
        int idx = tid + it * 512;      // 2048 chunks of 16B
        int row = idx >> 4;
        int c   = idx & 15;
        cp_async16(dst + row * 256 + ((c ^ (row & 7)) << 4),
                   (const char*)hi + row * 256 + c * 16);
    }
}

// load A/B fragments for one 16-wide k-step
__device__ __forceinline__ void load_frags(uint32_t sA, uint32_t bb, int ks,
                                           int m_base, int n_base, int lane,
                                           uint32_t af[2][4], uint32_t bf[4][2]) {
    int k0 = ks * 16;
    #pragma unroll
    for (int mt = 0; mt < 2; mt++) {
        int row = m_base + mt * 16 + (lane & 15);
        int k   = k0 + ((lane >> 4) << 3);
        ldmatrix_x4(af[mt], sA + sw_off(row, k));
    }
    #pragma unroll
    for (int np = 0; np < 2; np++) {
        uint32_t r4[4];
        int n = n_base + np * 16 + (lane & 7) + ((lane >> 4) << 3);
        int k = k0 + (((lane >> 3) & 1) << 3);
        ldmatrix_x4(r4, bb + sw_off(n, k));
        bf[np * 2 + 0][0] = r4[0]; bf[np * 2 + 0][1] = r4[1];
        bf[np * 2 + 1][0] = r4[2]; bf[np * 2 + 1][1] = r4[3];
    }
}

__global__ __launch_bounds__(512, 1) void gemm_negsum_kernel() {
    __shared__ int s_lab[BSZ];         // 16 KB static label cache
    __shared__ int s_np;               // per-CTA pair counter

    int cta  = blockIdx.x;
    int tid  = threadIdx.x;
    int wid  = tid >> 5;
    int lane = tid & 31;

    int s = cta * 14 + min(cta, 8);
    int e = s + 14 + (cta < 8 ? 1 : 0);

    uint32_t sA = smem_u32(smemB);
    uint2* my_pairs = &g_pairs[(size_t)cta * REG];

    int wm = wid & 3, wn = wid >> 2;            // 4x4 warp grid
    int m_base = wm * 32, n_base = wn * 32;
    int gid = lane >> 2, qid = lane & 3;

    int cur_bi = -1, prev_I0 = -1;
    float rsa[2][2] = {{0, 0}, {0, 0}};        // row-sum carry across same-bi tiles

    if (tid == 0) s_np = 0;
    // fill label cache (visibility via first in-loop __syncthreads)
    #pragma unroll
    for (int q = 0; q < BSZ / 512; q++) s_lab[tid + q * 512] = g_lab[tid + q * 512];

    {
        int bi0, bj0; tile_map(s, bi0, bj0);
        prefetch_tile(sA + TILE_B * (1 + s % 3), &g_Uhi[(size_t)bj0 * TS * DIM], tid);
        CP_COMMIT();
    }

    #pragma unroll 1
    for (int t = s; t < e; t++) {
        int bi, bj; tile_map(t, bi, bj);
        if (bi != cur_bi) {
            // flush row-sum carry for previous bi
            if (prev_I0 >= 0) {
                #pragma unroll
                for (int mt = 0; mt < 2; mt++)
                    #pragma unroll
                    for (int h = 0; h < 2; h++) {
                        float v = rsa[mt][h];
                        v += __shfl_xor_sync(0xffffffffu, v, 1);
                        v += __shfl_xor_sync(0xffffffffu, v, 2);
                        if (qid == 0)
                            atomicAdd(&g_S[prev_I0 + m_base + mt * 16 + h * 8 + gid], v);
                        rsa[mt][h] = 0.0f;
                    }
            }
            __syncthreads();   // all warps done reading sA before overwrite
            prefetch_tile(sA, &g_Uhi[(size_t)bi * TS * DIM], tid);
            CP_COMMIT();
            cur_bi = bi;
            prev_I0 = bi * TS;
        }
        if (t + 1 < e) {
            int bi2, bj2; tile_map(t + 1, bi2, bj2);
            prefetch_tile(sA + TILE_B * (1 + (t + 1) % 3),
                          &g_Uhi[(size_t)bj2 * TS * DIM], tid);
            CP_COMMIT();
            CP_WAIT(1);
        } else {
            CP_WAIT(0);
        }
        __syncthreads();

        bool diag = (bi == bj);
        int I0 = bi * TS, J0 = bj * TS;
        uint32_t bb = sA + TILE_B * (1 + t % 3);

        float acc[2][4][4];
        #pragma unroll
        for (int mt = 0; mt < 2; mt++)
            #pragma unroll
            for (int nt = 0; nt < 4; nt++)
                #pragma unroll
                for (int q = 0; q < 4; q++) acc[mt][nt][q] = 0.0f;

        // software-pipelined k-loop: frags(ks+1) load overlaps mma(ks)
        uint32_t afr[2][2][4], bfr[2][4][2];
        load_frags(sA, bb, 0, m_base, n_base, lane, afr[0], bfr[0]);
        #pragma unroll
        for (int ks = 0; ks < 8; ks++) {
            int cur = ks & 1;
            if (ks < 7)
                load_frags(sA, bb, ks + 1, m_base, n_base, lane,
                           afr[cur ^ 1], bfr[cur ^ 1]);
            #pragma unroll
            for (int mt = 0; mt < 2; mt++)
                #pragma unroll
                for (int nt = 0; nt < 4; nt++)
                    mma_16816_bf16(acc[mt][nt], afr[cur][mt], bfr[cur][nt]);
        }

        // ---- epilogue: exp2 + neg-mask sums, positive mask (labels: LDS) --
        int la[2][2], lb[4][2];
        #pragma unroll
        for (int mt = 0; mt < 2; mt++)
            #pragma unroll
            for (int h = 0; h < 2; h++)
                la[mt][h] = s_lab[(I0 + m_base + mt * 16 + h * 8 + gid) & (BSZ - 1)];
        #pragma unroll
        for (int nt = 0; nt < 4; nt++)
            #pragma unroll
            for (int qq = 0; qq < 2; qq++)
                lb[nt][qq] = s_lab[(J0 + n_base + nt * 8 + qid * 2 + qq) & (BSZ - 1)];

        uint32_t posmask = 0u;
        if (!diag) {
            float cs[4][2];
            #pragma unroll
            for (int nt = 0; nt < 4; nt++) cs[nt][0] = cs[nt][1] = 0.0f;
            #pragma unroll
            for (int mt = 0; mt < 2; mt++)
                #pragma unroll
                for (int nt = 0; nt < 4; nt++)
                    #pragma unroll
                    for (int h = 0; h < 2; h++)
                        #pragma unroll
                        for (int qq = 0; qq < 2; qq++) {
                            float d = acc[mt][nt][h * 2 + qq];
                            bool same = (la[mt][h] == lb[nt][qq]);
                            float ev = same ? 0.0f : ex2_fast(d * EXP2_SCL);
                            rsa[mt][h] += ev;
                            cs[nt][qq] += ev;
                            if (same)
                                posmask |= 1u << (mt * 16 + nt * 4 + h * 2 + qq);
                        }
            #pragma unroll
            for (int nt = 0; nt < 4; nt++)
                #pragma unroll
                for (int qq = 0; qq < 2; qq++) {
                    float v = cs[nt][qq];
                    v += __shfl_xor_sync(0xffffffffu, v, 4);
                    v += __shfl_xor_sync(0xffffffffu, v, 8);
                    v += __shfl_xor_sync(0xffffffffu, v, 16);
                    if (gid == 0)
                        atomicAdd(&g_S[J0 + n_base + nt * 8 + qid * 2 + qq], v);
                }
        } else {
            #pragma unroll
            for (int mt = 0; mt < 2; mt++)
                #pragma unroll
                for (int nt = 0; nt < 4; nt++)
                    #pragma unroll
                    for (int h = 0; h < 2; h++)
                        #pragma unroll
                        for (int qq = 0; qq < 2; qq++) {
                            int rloc = m_base + mt * 16 + h * 8 + gid;
                            int cloc = n_base + nt * 8 + qid * 2 + qq;
                            float d = acc[mt][nt][h * 2 + qq];
                            bool same = (la[mt][h] == lb[nt][qq]);
                            float ev = same ? 0.0f : ex2_fast(d * EXP2_SCL);
                            rsa[mt][h] += ev;
                            if (same && rloc < cloc)
                                posmask |= 1u << (mt * 16 + nt * 4 + h * 2 + qq);
                        }
        }

        // ---- pair append: SMEM counter gives per-lane slots directly ------
        {
            int cnt = __popc(posmask);
            int slot = 0;
            if (cnt) slot = atomicAdd(&s_np, cnt);
            if (posmask) {
                #pragma unroll
                for (int mt = 0; mt < 2; mt++)
                    #pragma unroll
                    for (int nt = 0; nt < 4; nt++)
                        #pragma unroll
                        for (int h = 0; h < 2; h++)
                            #pragma unroll
                            for (int qq = 0; qq < 2; qq++) {
                                int eidx = mt * 16 + nt * 4 + h * 2 + qq;
                                if ((posmask >> eidx) & 1u) {
                                    int rloc = m_base + mt * 16 + h * 8 + gid;
                                    int cloc = n_base + nt * 8 + qid * 2 + qq;
                                    float l = acc[mt][nt][h * 2 + qq] * INV_T;
                                    if (slot < REG) {
                                        uint32_t ij = ((uint32_t)(I0 + rloc) << 13)
                                                     | (uint32_t)(J0 + cloc);
                                        my_pairs[slot] =
                                            make_uint2(ij, __float_as_uint(l));
                                    }
                                    slot++;
                                }
                            }
            }
        }
    }

    // final row-sum flush
    if (prev_I0 >= 0) {
        #pragma unroll
        for (int mt = 0; mt < 2; mt++)
            #pragma unroll
            for (int h = 0; h < 2; h++) {
                float v = rsa[mt][h];
                v += __shfl_xor_sync(0xffffffffu, v, 1);
                v += __shfl_xor_sync(0xffffffffu, v, 2);
                if (qid == 0)
                    atomicAdd(&g_S[prev_I0 + m_base + mt * 16 + h * 8 + gid], v);
            }
    }
    __syncthreads();
    if (tid == 0) g_cta_np[cta] = s_np;
}

// ---------------------------------------------------------------------------
// Kernel C: one block per pair region; last block writes final scalar
// ---------------------------------------------------------------------------
__global__ void pair_loss_kernel(float* out) {
    int region = blockIdx.x;
    int n = min(g_cta_np[region], REG);
    const uint2* base = &g_pairs[(size_t)region * REG];

    float sum = 0.0f;
    for (int idx = threadIdx.x; idx < n; idx += blockDim.x) {
        uint2 en = base[idx];
        int i = (int)(en.x >> 13);
        int j = (int)(en.x & 8191u);
        float l = __uint_as_float(en.y);
        float ev = __expf(l);
        sum += 2.0f * l - __logf(g_S[i] + ev) - __logf(g_S[j] + ev);
    }
    #pragma unroll
    for (int o = 16; o > 0; o >>= 1) sum += __shfl_xor_sync(0xffffffffu, sum, o);
    __shared__ float ws[8];
    int wid = threadIdx.x >> 5, lane = threadIdx.x & 31;
    if (lane == 0) ws[wid] = sum;
    __syncthreads();
    if (threadIdx.x == 0) {
        float b = 0.0f;
        #pragma unroll
        for (int w = 0; w < 8; w++) b += ws[w];
        if (b != 0.0f) atomicAdd(&g_loss, (double)b);
        __threadfence();
        int old = atomicAdd(&g_done, 1);
        if (old == gridDim.x - 1)
            out[0] = (float)(-g_loss / (double)NROWS);
    }
}

extern "C" void kernel_launch(void* const* d_in, const int* in_sizes, int n_in,
                              void* d_out, int out_size) {
    const float* feat   = (const float*)d_in[0];
    const void*  labels = d_in[1];
    float*       out    = (float*)d_out;

    prep_kernel<<<1024, 256>>>(feat, labels);

    cudaFuncSetAttribute(gemm_negsum_kernel,
                         cudaFuncAttributeMaxDynamicSharedMemorySize, SM_TOTAL);
    gemm_negsum_kernel<<<NCTA, 512, SM_TOTAL>>>();

    pair_loss_kernel<<<NCTA, 256>>>(out);
}

// round 15
// speedup vs baseline: 1.1860x; 1.0296x over previous
#include <cuda_runtime.h>
#include <cuda_bf16.h>
#include <cstdint>
#include <math.h>

#define BSZ   4096
#define NROWS 8192
#define DIM   128
#define TS    128
#define LN2F  0.69314718055994531f
#define SC    4.5398160926f            // sqrt(log2(e)/0.07); dot*SC^2 = exp2 arg
#define NTILE 2080
#define NCTA  148
#define REG   32768                    // pairs per CTA region

// ---------------- scratch (__device__ globals; no allocs allowed) ----------
__device__ __nv_bfloat16  g_Uhi[NROWS * DIM];   // u * SC  (bf16)
__device__ float          g_S  [NROWS];
__device__ int            g_lab[BSZ];
__device__ int            g_cta_np[NCTA];
__device__ int            g_done;
__device__ uint2          g_pairs[NCTA * REG];  // {i<<13|j, bits(logit)}
__device__ double         g_loss;

// ---------------- helpers ---------------------------------------------------
__device__ __forceinline__ float ex2_fast(float x) {
    float r;
    asm("ex2.approx.ftz.f32 %0, %1;" : "=f"(r) : "f"(x));
    return r;
}
__device__ __forceinline__ uint32_t smem_u32(const void* p) {
    uint32_t a;
    asm("{ .reg .u64 t; cvta.to.shared.u64 t, %1; cvt.u32.u64 %0, t; }"
        : "=r"(a) : "l"(p));
    return a;
}
__device__ __forceinline__ void cp_async16(uint32_t saddr, const void* gp) {
    uint64_t ga;
    asm("cvta.to.global.u64 %0, %1;" : "=l"(ga) : "l"(gp));
    asm volatile("cp.async.cg.shared.global [%0], [%1], 16;"
                 :: "r"(saddr), "l"(ga));
}
#define CP_COMMIT()  asm volatile("cp.async.commit_group;" ::: "memory")
#define CP_WAIT(n)   asm volatile("cp.async.wait_group %0;" :: "n"(n) : "memory")

__device__ __forceinline__ void ldmatrix_x4(uint32_t* r, uint32_t addr) {
    asm volatile("ldmatrix.sync.aligned.m8n8.x4.shared.b16 {%0,%1,%2,%3}, [%4];"
                 : "=r"(r[0]), "=r"(r[1]), "=r"(r[2]), "=r"(r[3]) : "r"(addr));
}
__device__ __forceinline__ void mma_16816_bf16(float* d, const uint32_t* a,
                                               const uint32_t* b) {
    asm volatile(
        "mma.sync.aligned.m16n8k16.row.col.f32.bf16.bf16.f32 "
        "{%0,%1,%2,%3}, {%4,%5,%6,%7}, {%8,%9}, {%0,%1,%2,%3};"
        : "+f"(d[0]), "+f"(d[1]), "+f"(d[2]), "+f"(d[3])
        : "r"(a[0]), "r"(a[1]), "r"(a[2]), "r"(a[3]), "r"(b[0]), "r"(b[1]));
}

// tile index t (0..2079) -> (bi, bj) in row-major upper triangle
__device__ __forceinline__ void tile_map(int t, int& bi, int& bj) {
    int u = NTILE - t;
    float mf = (sqrtf(8.0f * (float)u + 1.0f) - 1.0f) * 0.5f;
    int m = (int)ceilf(mf);
    while (m * (m + 1) / 2 < u) m++;
    while (m > 1 && (m - 1) * m / 2 >= u) m--;
    bi = 64 - m;
    int off = bi * 64 - bi * (bi - 1) / 2;
    bj = bi + (t - off);
}

// ---------------------------------------------------------------------------
// Kernel A: normalize rows (2 rows/warp, loads batched); emit bf16*SC copy
// ---------------------------------------------------------------------------
__global__ void prep_kernel(const float* __restrict__ feat,
                            const void* __restrict__ labels_raw) {
    __shared__ int s_is64;
    int t    = blockIdx.x * blockDim.x + threadIdx.x;
    int warp = t >> 5;
    int lane = t & 31;

    if (threadIdx.x == 0) {
        const int* li = (const int*)labels_raw;
        bool is64 = true;
        #pragma unroll
        for (int q = 1; q < 16; q += 2) is64 &= (li[q] == 0);
        s_is64 = is64 ? 1 : 0;
    }
    if (t < NROWS) g_S[t] = 0.0f;
    if (t == 0) { g_loss = 0.0; g_done = 0; }
    __syncthreads();
    if (t < BSZ) {
        g_lab[t] = s_is64 ? (int)((const long long*)labels_raw)[t]
                          : ((const int*)labels_raw)[t];
    }

    int i0 = warp * 2;
    if (i0 >= NROWS) return;

    float4 f[2];
    #pragma unroll
    for (int r = 0; r < 2; r++) {
        int i = i0 + r;
        int v = i >> 12;
        int b = i & (BSZ - 1);
        f[r] = ((const float4*)&feat[(size_t)(b * 2 + v) * DIM])[lane];
    }
    #pragma unroll
    for (int r = 0; r < 2; r++) {
        float ss = f[r].x * f[r].x + f[r].y * f[r].y
                 + f[r].z * f[r].z + f[r].w * f[r].w;
        #pragma unroll
        for (int o = 16; o > 0; o >>= 1)
            ss += __shfl_xor_sync(0xffffffffu, ss, o);
        float rn = rsqrtf(ss) * SC;
        float u[4] = { f[r].x * rn, f[r].y * rn, f[r].z * rn, f[r].w * rn };
        __nv_bfloat16 hi[4];
        #pragma unroll
        for (int q = 0; q < 4; q++) hi[q] = __float2bfloat16(u[q]);
        ((uint2*)&g_Uhi[(size_t)(i0 + r) * DIM])[lane] =
            make_uint2(((uint32_t*)hi)[0], ((uint32_t*)hi)[1]);
    }
}

// ---------------------------------------------------------------------------
// Kernel B: persistent bf16 mma.sync GEMM, 512 threads (16 warps, 32x32
// warp tiles). A reused across a row; B in a 3-deep cp.async ring.
// acc is PRE-SCALED for exp2 (no per-element FMUL). Labels in SMEM;
// pipelined k-loop; pair append via SMEM counter into per-CTA region.
// ---------------------------------------------------------------------------
#define TILE_B   32768
#define SM_TOTAL (4 * TILE_B)          // A + 3 B ring buffers = 131072
extern __shared__ char smemB[];

__device__ __forceinline__ uint32_t sw_off(int row, int k_elem) {
    int chunk = k_elem >> 3;
    int within = k_elem & 7;
    return (uint32_t)(row * 256 + ((chunk ^ (row & 7)) << 4) + within * 2);
}

__device__ __forceinline__ void prefetch_tile(uint32_t dst,
                                              const __nv_bfloat16* hi,
                                              int tid) {
    #pragma unroll
    for (int it = 0; it < 4; it++) {
        int idx = tid + it * 512;      // 2048 chunks of 16B
        int row = idx >> 4;
        int c   = idx & 15;
        cp_async16(dst + row * 256 + ((c ^ (row & 7)) << 4),
                   (const char*)hi + row * 256 + c * 16);
    }
}

// load A/B fragments for one 16-wide k-step
__device__ __forceinline__ void load_frags(uint32_t sA, uint32_t bb, int ks,
                                           int m_base, int n_base, int lane,
                                           uint32_t af[2][4], uint32_t bf[4][2]) {
    int k0 = ks * 16;
    #pragma unroll
    for (int mt = 0; mt < 2; mt++) {
        int row = m_base + mt * 16 + (lane & 15);
        int k   = k0 + ((lane >> 4) << 3);
        ldmatrix_x4(af[mt], sA + sw_off(row, k));
    }
    #pragma unroll
    for (int np = 0; np < 2; np++) {
        uint32_t r4[4];
        int n = n_base + np * 16 + (lane & 7) + ((lane >> 4) << 3);
        int k = k0 + (((lane >> 3) & 1) << 3);
        ldmatrix_x4(r4, bb + sw_off(n, k));
        bf[np * 2 + 0][0] = r4[0]; bf[np * 2 + 0][1] = r4[1];
        bf[np * 2 + 1][0] = r4[2]; bf[np * 2 + 1][1] = r4[3];
    }
}

__global__ __launch_bounds__(512, 1) void gemm_negsum_kernel() {
    __shared__ int s_lab[BSZ];         // 16 KB static label cache
    __shared__ int s_np;               // per-CTA pair counter

    int cta  = blockIdx.x;
    int tid  = threadIdx.x;
    int wid  = tid >> 5;
    int lane = tid & 31;

    int s = cta * 14 + min(cta, 8);
    int e = s + 14 + (cta < 8 ? 1 : 0);

    uint32_t sA = smem_u32(smemB);
    uint2* my_pairs = &g_pairs[(size_t)cta * REG];

    int wm = wid & 3, wn = wid >> 2;            // 4x4 warp grid
    int m_base = wm * 32, n_base = wn * 32;
    int gid = lane >> 2, qid = lane & 3;

    int cur_bi = -1, prev_I0 = -1;
    float rsa[2][2] = {{0, 0}, {0, 0}};        // row-sum carry across same-bi tiles

    if (tid == 0) s_np = 0;
    // fill label cache (visibility via first in-loop __syncthreads)
    #pragma unroll
    for (int q = 0; q < BSZ / 512; q++) s_lab[tid + q * 512] = g_lab[tid + q * 512];

    {
        int bi0, bj0; tile_map(s, bi0, bj0);
        prefetch_tile(sA + TILE_B * (1 + s % 3), &g_Uhi[(size_t)bj0 * TS * DIM], tid);
        CP_COMMIT();
    }

    #pragma unroll 1
    for (int t = s; t < e; t++) {
        int bi, bj; tile_map(t, bi, bj);
        if (bi != cur_bi) {
            // flush row-sum carry for previous bi
            if (prev_I0 >= 0) {
                #pragma unroll
                for (int mt = 0; mt < 2; mt++)
                    #pragma unroll
                    for (int h = 0; h < 2; h++) {
                        float v = rsa[mt][h];
                        v += __shfl_xor_sync(0xffffffffu, v, 1);
                        v += __shfl_xor_sync(0xffffffffu, v, 2);
                        if (qid == 0)
                            atomicAdd(&g_S[prev_I0 + m_base + mt * 16 + h * 8 + gid], v);
                        rsa[mt][h] = 0.0f;
                    }
            }
            __syncthreads();   // all warps done reading sA before overwrite
            prefetch_tile(sA, &g_Uhi[(size_t)bi * TS * DIM], tid);
            CP_COMMIT();
            cur_bi = bi;
            prev_I0 = bi * TS;
        }
        if (t + 1 < e) {
            int bi2, bj2; tile_map(t + 1, bi2, bj2);
            prefetch_tile(sA + TILE_B * (1 + (t + 1) % 3),
                          &g_Uhi[(size_t)bj2 * TS * DIM], tid);
            CP_COMMIT();
            CP_WAIT(1);
        } else {
            CP_WAIT(0);
        }
        __syncthreads();

        bool diag = (bi == bj);
        int I0 = bi * TS, J0 = bj * TS;
        uint32_t bb = sA + TILE_B * (1 + t % 3);

        float acc[2][4][4];
        #pragma unroll
        for (int mt = 0; mt < 2; mt++)
            #pragma unroll
            for (int nt = 0; nt < 4; nt++)
                #pragma unroll
                for (int q = 0; q < 4; q++) acc[mt][nt][q] = 0.0f;

        // software-pipelined k-loop: frags(ks+1) load overlaps mma(ks)
        uint32_t afr[2][2][4], bfr[2][4][2];
        load_frags(sA, bb, 0, m_base, n_base, lane, afr[0], bfr[0]);
        #pragma unroll
        for (int ks = 0; ks < 8; ks++) {
            int cur = ks & 1;
            if (ks < 7)
                load_frags(sA, bb, ks + 1, m_base, n_base, lane,
                           afr[cur ^ 1], bfr[cur ^ 1]);
            #pragma unroll
            for (int mt = 0; mt < 2; mt++)
                #pragma unroll
                for (int nt = 0; nt < 4; nt++)
                    mma_16816_bf16(acc[mt][nt], afr[cur][mt], bfr[cur][nt]);
        }

        // ---- epilogue: ex2(acc) directly (acc pre-scaled), neg-mask sums --
        int la[2][2], lb[4][2];
        #pragma unroll
        for (int mt = 0; mt < 2; mt++)
            #pragma unroll
            for (int h = 0; h < 2; h++)
                la[mt][h] = s_lab[(I0 + m_base + mt * 16 + h * 8 + gid) & (BSZ - 1)];
        #pragma unroll
        for (int nt = 0; nt < 4; nt++)
            #pragma unroll
            for (int qq = 0; qq < 2; qq++)
                lb[nt][qq] = s_lab[(J0 + n_base + nt * 8 + qid * 2 + qq) & (BSZ - 1)];

        uint32_t posmask = 0u;
        if (!diag) {
            float cs[4][2];
            #pragma unroll
            for (int nt = 0; nt < 4; nt++) cs[nt][0] = cs[nt][1] = 0.0f;
            #pragma unroll
            for (int mt = 0; mt < 2; mt++)
                #pragma unroll
                for (int nt = 0; nt < 4; nt++)
                    #pragma unroll
                    for (int h = 0; h < 2; h++)
                        #pragma unroll
                        for (int qq = 0; qq < 2; qq++) {
                            float d = acc[mt][nt][h * 2 + qq];
                            bool same = (la[mt][h] == lb[nt][qq]);
                            float ev = same ? 0.0f : ex2_fast(d);
                            rsa[mt][h] += ev;
                            cs[nt][qq] += ev;
                            if (same)
                                posmask |= 1u << (mt * 16 + nt * 4 + h * 2 + qq);
                        }
            #pragma unroll
            for (int nt = 0; nt < 4; nt++)
                #pragma unroll
                for (int qq = 0; qq < 2; qq++) {
                    float v = cs[nt][qq];
                    v += __shfl_xor_sync(0xffffffffu, v, 4);
                    v += __shfl_xor_sync(0xffffffffu, v, 8);
                    v += __shfl_xor_sync(0xffffffffu, v, 16);
                    if (gid == 0)
                        atomicAdd(&g_S[J0 + n_base + nt * 8 + qid * 2 + qq], v);
                }
        } else {
            #pragma unroll
            for (int mt = 0; mt < 2; mt++)
                #pragma unroll
                for (int nt = 0; nt < 4; nt++)
                    #pragma unroll
                    for (int h = 0; h < 2; h++)
                        #pragma unroll
                        for (int qq = 0; qq < 2; qq++) {
                            int rloc = m_base + mt * 16 + h * 8 + gid;
                            int cloc = n_base + nt * 8 + qid * 2 + qq;
                            float d = acc[mt][nt][h * 2 + qq];
                            bool same = (la[mt][h] == lb[nt][qq]);
                            float ev = same ? 0.0f : ex2_fast(d);
                            rsa[mt][h] += ev;
                            if (same && rloc < cloc)
                                posmask |= 1u << (mt * 16 + nt * 4 + h * 2 + qq);
                        }
        }

        // ---- pair append: SMEM counter gives per-lane slots directly ------
        {
            int cnt = __popc(posmask);
            int slot = 0;
            if (cnt) slot = atomicAdd(&s_np, cnt);
            if (posmask) {
                #pragma unroll
                for (int mt = 0; mt < 2; mt++)
                    #pragma unroll
                    for (int nt = 0; nt < 4; nt++)
                        #pragma unroll
                        for (int h = 0; h < 2; h++)
                            #pragma unroll
                            for (int qq = 0; qq < 2; qq++) {
                                int eidx = mt * 16 + nt * 4 + h * 2 + qq;
                                if ((posmask >> eidx) & 1u) {
                                    int rloc = m_base + mt * 16 + h * 8 + gid;
                                    int cloc = n_base + nt * 8 + qid * 2 + qq;
                                    float l = acc[mt][nt][h * 2 + qq] * LN2F;
                                    if (slot < REG) {
                                        uint32_t ij = ((uint32_t)(I0 + rloc) << 13)
                                                     | (uint32_t)(J0 + cloc);
                                        my_pairs[slot] =
                                            make_uint2(ij, __float_as_uint(l));
                                    }
                                    slot++;
                                }
                            }
            }
        }
    }

    // final row-sum flush
    if (prev_I0 >= 0) {
        #pragma unroll
        for (int mt = 0; mt < 2; mt++)
            #pragma unroll
            for (int h = 0; h < 2; h++) {
                float v = rsa[mt][h];
                v += __shfl_xor_sync(0xffffffffu, v, 1);
                v += __shfl_xor_sync(0xffffffffu, v, 2);
                if (qid == 0)
                    atomicAdd(&g_S[prev_I0 + m_base + mt * 16 + h * 8 + gid], v);
            }
    }
    __syncthreads();
    if (tid == 0) g_cta_np[cta] = s_np;
}

// ---------------------------------------------------------------------------
// Kernel C: one block per pair region; last block writes final scalar
// ---------------------------------------------------------------------------
__global__ void pair_loss_kernel(float* out) {
    int region = blockIdx.x;
    int n = min(g_cta_np[region], REG);
    const uint2* base = &g_pairs[(size_t)region * REG];

    float sum = 0.0f;
    for (int idx = threadIdx.x; idx < n; idx += blockDim.x) {
        uint2 en = base[idx];
        int i = (int)(en.x >> 13);
        int j = (int)(en.x & 8191u);
        float l = __uint_as_float(en.y);
        float ev = __expf(l);
        sum += 2.0f * l - __logf(g_S[i] + ev) - __logf(g_S[j] + ev);
    }
    #pragma unroll
    for (int o = 16; o > 0; o >>= 1) sum += __shfl_xor_sync(0xffffffffu, sum, o);
    __shared__ float ws[8];
    int wid = threadIdx.x >> 5, lane = threadIdx.x & 31;
    if (lane == 0) ws[wid] = sum;
    __syncthreads();
    if (threadIdx.x == 0) {
        float b = 0.0f;
        #pragma unroll
        for (int w = 0; w < 8; w++) b += ws[w];
        if (b != 0.0f) atomicAdd(&g_loss, (double)b);
        __threadfence();
        int old = atomicAdd(&g_done, 1);
        if (old == gridDim.x - 1)
            out[0] = (float)(-g_loss / (double)NROWS);
    }
}

extern "C" void kernel_launch(void* const* d_in, const int* in_sizes, int n_in,
                              void* d_out, int out_size) {
    const float* feat   = (const float*)d_in[0];
    const void*  labels = d_in[1];
    float*       out    = (float*)d_out;

    prep_kernel<<<512, 256>>>(feat, labels);

    cudaFuncSetAttribute(gemm_negsum_kernel,
                         cudaFuncAttributeMaxDynamicSharedMemorySize, SM_TOTAL);
    gemm_negsum_kernel<<<NCTA, 512, SM_TOTAL>>>();

    pair_loss_kernel<<<NCTA, 256>>>(out);
}